// round 15
// baseline (speedup 1.0000x reference)
#include <cuda_runtime.h>
#include <cuda_fp16.h>

// ----------------------------------------------------------------------------
// KB_Mapping_19361712570541 — HMMA fp16 2-term split, persistent CTAs,
// fp16 intermediates, prefetch pipelines, mask fused into MMA sweep,
// K3 dual-GEMM interleaved k-loop.
//   K1: A1 = fp16(x) [prefetched, 1 pass]; A0 = relu(dw1(A1 smem));
//       t1 = relu(A0 @ W1^T) [compressed regs];
//       b2 = mask(relu(A1 @ W2^T) + t1) -> g_b2h; side-writes g_xh.
//   K2: b2p = relu(relu(dw2(b2h)) @ W3^T) -> g_b2ph
//   K3: out = relu(xh @ Wfa^T + b2ph @ Wfb^T)  (single interleaved k-loop)
// GEMMs: A@W ~= Afp16 @ Whi + Afp16 @ Wlo  (W split ~22 mantissa bits).
// Warp map (16 warps, 4x4): rows (warp&3)*32..+32, cols (warp>>2)*32..+32.
// ----------------------------------------------------------------------------

#define NTOK   131072
#define CCH    128
#define TILE_M 128
#define NTILES (NTOK / TILE_M)   // 1024
#define NT     512
#define PITCHB 136               // fp16 smem pitch (ldmatrix conflict-free)
#define WBYTES (CCH * PITCHB * 2)   // 34816 bytes per fp16 matrix tile
#define GRID1  148
#define GRID2  296

typedef unsigned int u32;

// ---------------- device scratch ---------------------------------------------
__device__ __half g_xh  [(size_t)NTOK * CCH];   // fp16(x), written by K1
__device__ __half g_b2h [(size_t)NTOK * CCH];   // fp16(b2)
__device__ __half g_b2ph[(size_t)NTOK * CCH];   // fp16(b2p)
__device__ __half g_whi[5][CCH * CCH];          // row-major [o][k] hi part
__device__ __half g_wlo[5][CCH * CCH];          // lo part (residual)

// ---------------- PTX helpers -------------------------------------------------
__device__ __forceinline__ u32 smem_u32(const void* p) {
    u32 a;
    asm("{ .reg .u64 t; cvta.to.shared.u64 t, %1; cvt.u32.u64 %0, t; }"
        : "=r"(a) : "l"(p));
    return a;
}
#define LDM4(r, a)                                                          \
    asm volatile("ldmatrix.sync.aligned.m8n8.x4.shared.b16 {%0,%1,%2,%3}, [%4];" \
                 : "=r"((r)[0]), "=r"((r)[1]), "=r"((r)[2]), "=r"((r)[3])   \
                 : "r"(a))
#define MMA(c, a, b0, b1)                                                   \
    asm volatile("mma.sync.aligned.m16n8k16.row.col.f32.f16.f16.f32 "       \
                 "{%0,%1,%2,%3}, {%4,%5,%6,%7}, {%8,%9}, {%0,%1,%2,%3};"    \
                 : "+f"((c)[0]), "+f"((c)[1]), "+f"((c)[2]), "+f"((c)[3])   \
                 : "r"((a)[0]), "r"((a)[1]), "r"((a)[2]), "r"((a)[3]),      \
                   "r"(b0), "r"(b1))

// ---------------- threefry-2x32 partitionable keep-bit (validated R5) ---------
__device__ __forceinline__ u32 rotl32(u32 x, int r) { return __funnelshift_l(x, x, r); }
__device__ __forceinline__ u32 keepbit(u32 fidx) {
    const u32 K0 = 0u, K1 = 42u, K2 = 0u ^ 42u ^ 0x1BD11BDAu;
    u32 x0 = 0u + K0;      // counts_hi = 0
    u32 x1 = fidx + K1;    // counts_lo = f
#define TF_R4(a,b,c,d)                               \
    x0 += x1; x1 = rotl32(x1,(a)); x1 ^= x0;         \
    x0 += x1; x1 = rotl32(x1,(b)); x1 ^= x0;         \
    x0 += x1; x1 = rotl32(x1,(c)); x1 ^= x0;         \
    x0 += x1; x1 = rotl32(x1,(d)); x1 ^= x0;
    TF_R4(13,15,26, 6);  x0 += K1; x1 += K2 + 1u;
    TF_R4(17,29,16,24);  x0 += K2; x1 += K0 + 2u;
    TF_R4(13,15,26, 6);  x0 += K0; x1 += K1 + 3u;
    TF_R4(17,29,16,24);  x0 += K1; x1 += K2 + 4u;
    TF_R4(13,15,26, 6);  x0 += K2; x1 += K0 + 5u;
#undef TF_R4
    return (~(x0 ^ x1)) >> 31;   // 1 = keep (MSB of xor-fold == 0)
}

// ---------------- weight prep: fp16 hi/lo split, row-major [o][k] ------------
__global__ void kPrep(const float* __restrict__ w1, const float* __restrict__ w2,
                      const float* __restrict__ w3, const float* __restrict__ wf) {
    int e = blockIdx.x * blockDim.x + threadIdx.x;
    if (e >= 5 * CCH * CCH) return;
    int mat = e >> 14, idx = e & 16383, o = idx >> 7, k = idx & 127;
    float v;
    if      (mat == 0) v = w1[idx];              // w_b1_pw
    else if (mat == 1) v = w2[idx];              // w_b2_1x1
    else if (mat == 2) v = w3[idx];              // w_b2_pw
    else if (mat == 3) v = wf[o * 256 + k];      // w_fusion[:, :128]
    else               v = wf[o * 256 + 128 + k];// w_fusion[:, 128:]
    __half h = __float2half_rn(v);
    __half l = __float2half_rn(v - __half2float(h));
    g_whi[mat][idx] = h;
    g_wlo[mat][idx] = l;
}

// ---------------- tile helpers ------------------------------------------------
__device__ __forceinline__ void load8(float v[8], const float* __restrict__ p,
                                      long row, int k0) {
    if ((unsigned long)row < (unsigned long)NTOK) {
        float4 a = *(const float4*)(p + row * CCH + k0);
        float4 b = *(const float4*)(p + row * CCH + k0 + 4);
        v[0]=a.x; v[1]=a.y; v[2]=a.z; v[3]=a.w;
        v[4]=b.x; v[5]=b.y; v[6]=b.z; v[7]=b.w;
    } else {
#pragma unroll
        for (int j = 0; j < 8; j++) v[j] = 0.f;
    }
}
__device__ __forceinline__ void load8h(float v[8], const __half* __restrict__ p,
                                       long row, int k0) {
    if ((unsigned long)row < (unsigned long)NTOK) {
        uint4 r = *(const uint4*)(p + row * CCH + k0);
        const __half2* h2 = (const __half2*)&r;
#pragma unroll
        for (int j = 0; j < 4; j++) {
            float2 f = __half22float2(h2[j]);
            v[2 * j] = f.x; v[2 * j + 1] = f.y;
        }
    } else {
#pragma unroll
        for (int j = 0; j < 8; j++) v[j] = 0.f;
    }
}
__device__ __forceinline__ void unpack8s(float v[8], const char* p) {
    uint4 r = *(const uint4*)p;
    const __half2* h2 = (const __half2*)&r;
#pragma unroll
    for (int j = 0; j < 4; j++) {
        float2 f = __half22float2(h2[j]);
        v[2 * j] = f.x; v[2 * j + 1] = f.y;
    }
}
__device__ __forceinline__ uint4 pack8h(const float v[8]) {
    uint4 r;
    __half2* h2 = (__half2*)&r;
#pragma unroll
    for (int j = 0; j < 4; j++)
        h2[j] = __floats2half2_rn(v[2 * j], v[2 * j + 1]);
    return r;
}

// Copy one pre-split weight matrix into pitched smem (hi+lo).
__device__ __forceinline__ void loadW(char* hd, char* ld, int mat, int tid) {
    const uint4* sh = (const uint4*)g_whi[mat];
    const uint4* sl = (const uint4*)g_wlo[mat];
#pragma unroll
    for (int q = tid; q < 2048; q += NT) {             // 16 uint4 per row
        int n = q >> 4, k0 = (q & 15) << 3;
        u32 doff = (u32)(n * PITCHB + k0) * 2;
        *(uint4*)(hd + doff) = sh[q];
        *(uint4*)(ld + doff) = sl[q];
    }
}

// K2 fill from fp16 source with fused dw + relu.
__device__ __forceinline__ void fillA_h(char* A, const __half* __restrict__ src,
                                        int base, const float* taps, int tid) {
#pragma unroll 1
    for (int q = tid; q < 2048; q += NT) {
        int m = q >> 4, k0 = (q & 15) << 3;
        long gr = (long)base + m;
        float a[8], b[8], c[8], v[8];
        load8h(a, src, gr - 1, k0);
        load8h(b, src, gr,     k0);
        load8h(c, src, gr + 1, k0);
#pragma unroll
        for (int j = 0; j < 8; j++) {
            int ch = k0 + j;
            v[j] = fmaxf(taps[ch] * a[j] + taps[CCH + ch] * b[j]
                         + taps[2 * CCH + ch] * c[j], 0.f);
        }
        *(uint4*)(A + (u32)(m * PITCHB + k0) * 2) = pack8h(v);
    }
}

// 2-term split GEMM sweep: acc += A @ Whi + A @ Wlo.
// Warp: rows [m0, m0+32) (2 m-tiles) x cols [c0w, c0w+32) (2 n-pairs).
__device__ __forceinline__ void sweep(u32 as, u32 whs, u32 wls,
                                      int m0, int c0w, int lane, float (*acc)[4]) {
    const u32 arow  = (u32)(m0 + (lane & 7) + (lane & 8));
    const u32 acolb = (u32)((lane & 16) >> 1);             // 0 or 8
    const u32 brow0 = (u32)((lane & 7) + ((lane & 16) >> 1));
    const u32 astride = (u32)(16 * PITCHB * 2);            // 16 rows of A
#pragma unroll 2
    for (int k = 0; k < 8; k++) {
        u32 aoff = (arow * PITCHB + (u32)k * 16 + acolb) * 2;
        u32 a0[4], a1[4];
        LDM4(a0, as + aoff);
        LDM4(a1, as + aoff + astride);
        u32 bcol = ((u32)k * 16 + (u32)(lane & 8)) * 2;
        u32 boff0 = ((u32)c0w        + brow0) * (PITCHB * 2) + bcol;
        u32 boff1 = ((u32)(c0w + 16) + brow0) * (PITCHB * 2) + bcol;
        u32 bh0[4], bl0[4], bh1[4], bl1[4];
        LDM4(bh0, whs + boff0);
        LDM4(bl0, wls + boff0);
        LDM4(bh1, whs + boff1);
        LDM4(bl1, wls + boff1);
        MMA(acc[0], a0, bh0[0], bh0[1]);
        MMA(acc[0], a0, bl0[0], bl0[1]);
        MMA(acc[1], a0, bh0[2], bh0[3]);
        MMA(acc[1], a0, bl0[2], bl0[3]);
        MMA(acc[2], a0, bh1[0], bh1[1]);
        MMA(acc[2], a0, bl1[0], bl1[1]);
        MMA(acc[3], a0, bh1[2], bh1[3]);
        MMA(acc[3], a0, bl1[2], bl1[3]);
        MMA(acc[4], a1, bh0[0], bh0[1]);
        MMA(acc[4], a1, bl0[0], bl0[1]);
        MMA(acc[5], a1, bh0[2], bh0[3]);
        MMA(acc[5], a1, bl0[2], bl0[3]);
        MMA(acc[6], a1, bh1[0], bh1[1]);
        MMA(acc[6], a1, bl1[0], bl1[1]);
        MMA(acc[7], a1, bh1[2], bh1[3]);
        MMA(acc[7], a1, bl1[2], bl1[3]);
    }
}

// Dual-source interleaved sweep: acc += A0@(Wh0+Wl0) + A1@(Wh1+Wl1).
// One k-loop, 12 LDSM + 32 MMA per iteration (K3's two GEMMs share acc).
__device__ __forceinline__ void sweep_dual(u32 as0, u32 as1,
                                           u32 wh0, u32 wl0, u32 wh1, u32 wl1,
                                           int m0, int c0w, int lane,
                                           float (*acc)[4]) {
    const u32 arow  = (u32)(m0 + (lane & 7) + (lane & 8));
    const u32 acolb = (u32)((lane & 16) >> 1);
    const u32 brow0 = (u32)((lane & 7) + ((lane & 16) >> 1));
    const u32 astride = (u32)(16 * PITCHB * 2);
#pragma unroll 1
    for (int k = 0; k < 8; k++) {
        u32 aoff = (arow * PITCHB + (u32)k * 16 + acolb) * 2;
        u32 x0[4], x1[4], y0[4], y1[4];
        LDM4(x0, as0 + aoff);
        LDM4(x1, as0 + aoff + astride);
        LDM4(y0, as1 + aoff);
        LDM4(y1, as1 + aoff + astride);
        u32 bcol = ((u32)k * 16 + (u32)(lane & 8)) * 2;
        u32 boff0 = ((u32)c0w        + brow0) * (PITCHB * 2) + bcol;
        u32 boff1 = ((u32)(c0w + 16) + brow0) * (PITCHB * 2) + bcol;
        u32 p00[4], p01[4], p10[4], p11[4];
        u32 q00[4], q01[4], q10[4], q11[4];
        LDM4(p00, wh0 + boff0);
        LDM4(p01, wl0 + boff0);
        LDM4(p10, wh0 + boff1);
        LDM4(p11, wl0 + boff1);
        LDM4(q00, wh1 + boff0);
        LDM4(q01, wl1 + boff0);
        LDM4(q10, wh1 + boff1);
        LDM4(q11, wl1 + boff1);
        // source 0 (A0 @ W0)
        MMA(acc[0], x0, p00[0], p00[1]);
        MMA(acc[0], x0, p01[0], p01[1]);
        MMA(acc[1], x0, p00[2], p00[3]);
        MMA(acc[1], x0, p01[2], p01[3]);
        MMA(acc[2], x0, p10[0], p10[1]);
        MMA(acc[2], x0, p11[0], p11[1]);
        MMA(acc[3], x0, p10[2], p10[3]);
        MMA(acc[3], x0, p11[2], p11[3]);
        MMA(acc[4], x1, p00[0], p00[1]);
        MMA(acc[4], x1, p01[0], p01[1]);
        MMA(acc[5], x1, p00[2], p00[3]);
        MMA(acc[5], x1, p01[2], p01[3]);
        MMA(acc[6], x1, p10[0], p10[1]);
        MMA(acc[6], x1, p11[0], p11[1]);
        MMA(acc[7], x1, p10[2], p10[3]);
        MMA(acc[7], x1, p11[2], p11[3]);
        // source 1 (A1 @ W1)
        MMA(acc[0], y0, q00[0], q00[1]);
        MMA(acc[0], y0, q01[0], q01[1]);
        MMA(acc[1], y0, q00[2], q00[3]);
        MMA(acc[1], y0, q01[2], q01[3]);
        MMA(acc[2], y0, q10[0], q10[1]);
        MMA(acc[2], y0, q11[0], q11[1]);
        MMA(acc[3], y0, q10[2], q10[3]);
        MMA(acc[3], y0, q11[2], q11[3]);
        MMA(acc[4], y1, q00[0], q00[1]);
        MMA(acc[4], y1, q01[0], q01[1]);
        MMA(acc[5], y1, q00[2], q00[3]);
        MMA(acc[5], y1, q01[2], q01[3]);
        MMA(acc[6], y1, q10[0], q10[1]);
        MMA(acc[6], y1, q11[0], q11[1]);
        MMA(acc[7], y1, q10[2], q10[3]);
        MMA(acc[7], y1, q11[2], q11[3]);
    }
}

// Sweep variant with threefry mask fused into the k-loop: iteration k also
// computes the 4 keep-bits of output fragment k (rides idle issue slots).
__device__ __forceinline__ void sweep_mask(u32 as, u32 whs, u32 wls,
                                           int m0, int c0w, int lane,
                                           int base, int g, int t,
                                           float (*acc)[4], u32* mbout) {
    const u32 arow  = (u32)(m0 + (lane & 7) + (lane & 8));
    const u32 acolb = (u32)((lane & 16) >> 1);
    const u32 brow0 = (u32)((lane & 7) + ((lane & 16) >> 1));
    const u32 astride = (u32)(16 * PITCHB * 2);
    u32 mb = 0;
#pragma unroll 2
    for (int k = 0; k < 8; k++) {
        u32 aoff = (arow * PITCHB + (u32)k * 16 + acolb) * 2;
        u32 a0[4], a1[4];
        LDM4(a0, as + aoff);
        LDM4(a1, as + aoff + astride);
        u32 bcol = ((u32)k * 16 + (u32)(lane & 8)) * 2;
        u32 boff0 = ((u32)c0w        + brow0) * (PITCHB * 2) + bcol;
        u32 boff1 = ((u32)(c0w + 16) + brow0) * (PITCHB * 2) + bcol;
        u32 bh0[4], bl0[4], bh1[4], bl1[4];
        LDM4(bh0, whs + boff0);
        LDM4(bl0, wls + boff0);
        LDM4(bh1, whs + boff1);
        LDM4(bl1, wls + boff1);
        MMA(acc[0], a0, bh0[0], bh0[1]);
        MMA(acc[0], a0, bl0[0], bl0[1]);
        MMA(acc[1], a0, bh0[2], bh0[3]);
        MMA(acc[1], a0, bl0[2], bl0[3]);
        MMA(acc[2], a0, bh1[0], bh1[1]);
        MMA(acc[2], a0, bl1[0], bl1[1]);
        MMA(acc[3], a0, bh1[2], bh1[3]);
        MMA(acc[3], a0, bl1[2], bl1[3]);
        MMA(acc[4], a1, bh0[0], bh0[1]);
        MMA(acc[4], a1, bl0[0], bl0[1]);
        MMA(acc[5], a1, bh0[2], bh0[3]);
        MMA(acc[5], a1, bl0[2], bl0[3]);
        MMA(acc[6], a1, bh1[0], bh1[1]);
        MMA(acc[6], a1, bl1[0], bl1[1]);
        MMA(acc[7], a1, bh1[2], bh1[3]);
        MMA(acc[7], a1, bl1[2], bl1[3]);
        // fragment k mask bits: flat index = col*131072 + row
        {
            u32 r0 = (u32)(base + m0 + (k >> 2) * 16 + g);
            u32 c0 = (u32)(c0w + (k & 3) * 8 + t * 2);
            u32 fb = (c0 << 17) + r0;
            mb |= keepbit(fb)                    << (k * 4 + 0);
            mb |= keepbit(fb + (1u << 17))       << (k * 4 + 1);
            mb |= keepbit(fb + 8u)               << (k * 4 + 2);
            mb |= keepbit(fb + (1u << 17) + 8u)  << (k * 4 + 3);
        }
    }
    *mbout = mb;
}

#define ZACC(a) { _Pragma("unroll") for (int _i = 0; _i < 8; _i++) \
                  _Pragma("unroll") for (int _j = 0; _j < 4; _j++) (a)[_i][_j] = 0.f; }

// Shared-memory sizes
#define SM1 (6 * WBYTES + 3 * CCH * 4 + 4 * PITCHB)  // W1h/l W2h/l A0 A1 taps halo
#define SM2 (3 * WBYTES + 3 * CCH * 4)               // W3 h/l, A, taps
#define SM3 (6 * WBYTES)                             // Wfa h/l, Wfb h/l, A0, A1

// ---------------- K1 ----------------------------------------------------------
__device__ __forceinline__ void prefK1(uint4 pf[4][2], const float* __restrict__ x,
                                       int base, int tid) {
#pragma unroll
    for (int c = 0; c < 4; c++) {
        int q = tid + c * NT;
        int m = q >> 4, k0 = (q & 15) << 3;
        const float* p = x + (size_t)(base + m) * CCH + k0;
        pf[c][0] = *(const uint4*)p;
        pf[c][1] = *(const uint4*)(p + 4);
    }
}

__global__ void __launch_bounds__(NT)
K1(const float* __restrict__ x, const float* __restrict__ wdw) {
    extern __shared__ char sm[];
    char* W1h = sm;
    char* W1l = sm + WBYTES;
    char* W2h = sm + 2 * WBYTES;
    char* W2l = sm + 3 * WBYTES;
    char* A0  = sm + 4 * WBYTES;
    char* A1  = sm + 5 * WBYTES;
    float* taps = (float*)(sm + 6 * WBYTES);
    char* haloH = sm + 6 * WBYTES + 3 * CCH * 4;   // 2 rows x PITCHB fp16

    const int tid = threadIdx.x, lane = tid & 31, warp = tid >> 5;
    const int m0 = (warp & 3) * 32, c0w = (warp >> 2) * 32;
    const int g = lane >> 2, t = lane & 3;

    loadW(W1h, W1l, 0, tid);
    loadW(W2h, W2l, 1, tid);
    for (int e = tid; e < 3 * CCH; e += NT)
        taps[e] = wdw[(e & 127) * 9 + (e >> 7) * 3 + 1];

    const u32 a0s = smem_u32(A0), a1s = smem_u32(A1);
    const u32 w1hs = smem_u32(W1h), w1ls = smem_u32(W1l);
    const u32 w2hs = smem_u32(W2h), w2ls = smem_u32(W2l);

    uint4 pf[4][2];
    int tile = blockIdx.x;
    if (tile < NTILES) prefK1(pf, x, tile * TILE_M, tid);

    for (; tile < NTILES; tile += gridDim.x) {
        const int base = tile * TILE_M;

        // stage A1 = fp16(x) from prefetch; side-write g_xh; halo rows
#pragma unroll
        for (int c = 0; c < 4; c++) {
            int q = tid + c * NT;
            int m = q >> 4, k0 = (q & 15) << 3;
            float v[8];
            const float* f = (const float*)pf[c];
#pragma unroll
            for (int j = 0; j < 8; j++) v[j] = f[j];
            uint4 hx = pack8h(v);
            *(uint4*)(A1 + (u32)(m * PITCHB + k0) * 2) = hx;
            *(uint4*)(g_xh + (size_t)(base + m) * CCH + k0) = hx;
        }
        if (tid < 32) {
            int sel = tid >> 4;              // 0: base-1, 1: base+TILE_M
            int k0 = (tid & 15) << 3;
            long gr = sel ? (long)base + TILE_M : (long)base - 1;
            float v[8];
            load8(v, x, gr, k0);
            *(uint4*)(haloH + (u32)(sel * PITCHB + k0) * 2) = pack8h(v);
        }
        __syncthreads();

        // A0 = fp16(relu(dw1(A1)))  (all-smem reads)
#pragma unroll 1
        for (int c = 0; c < 4; c++) {
            int q = tid + c * NT;
            int m = q >> 4, k0 = (q & 15) << 3;
            const char* rm = (m == 0) ? haloH + (u32)k0 * 2
                                      : A1 + (u32)((m - 1) * PITCHB + k0) * 2;
            const char* rp = (m == TILE_M - 1)
                                      ? haloH + (u32)(PITCHB + k0) * 2
                                      : A1 + (u32)((m + 1) * PITCHB + k0) * 2;
            float a[8], b[8], cc[8], v[8];
            unpack8s(a, rm);
            unpack8s(b, A1 + (u32)(m * PITCHB + k0) * 2);
            unpack8s(cc, rp);
#pragma unroll
            for (int j = 0; j < 8; j++) {
                int ch = k0 + j;
                v[j] = fmaxf(taps[ch] * a[j] + taps[CCH + ch] * b[j]
                             + taps[2 * CCH + ch] * cc[j], 0.f);
            }
            *(uint4*)(A0 + (u32)(m * PITCHB + k0) * 2) = pack8h(v);
        }
        __syncthreads();

        // issue next tile's x loads; they fly during both sweeps
        int ntile = tile + gridDim.x;
        if (ntile < NTILES) prefK1(pf, x, ntile * TILE_M, tid);

        float acc[8][4];
        ZACC(acc);
        sweep(a0s, w1hs, w1ls, m0, c0w, lane, acc);   // t1 = A0 @ W1^T

        // compress relu(t1) to fp16 regs (b2 is stored fp16 anyway)
        u32 t1h[16];
#pragma unroll
        for (int f = 0; f < 8; f++) {
            __half2 lo = __floats2half2_rn(fmaxf(acc[f][0], 0.f), fmaxf(acc[f][1], 0.f));
            __half2 hi = __floats2half2_rn(fmaxf(acc[f][2], 0.f), fmaxf(acc[f][3], 0.f));
            t1h[2 * f]     = *(u32*)&lo;
            t1h[2 * f + 1] = *(u32*)&hi;
        }

        ZACC(acc);
        u32 mb;
        sweep_mask(a1s, w2hs, w2ls, m0, c0w, lane, base, g, t, acc, &mb);

        // b2 = mask(relu(accX) + t1) -> g_b2h (fp16)
#pragma unroll
        for (int f = 0; f < 8; f++) {
            const int mt = f >> 2, nt = f & 3;
            const int r0 = base + m0 + mt * 16 + g;
            const int c0 = c0w + nt * 8 + t * 2;
            float2 tl = __half22float2(*(__half2*)&t1h[2 * f]);
            float2 th = __half22float2(*(__half2*)&t1h[2 * f + 1]);
            float v00 = fmaxf(acc[f][0], 0.f) + tl.x;
            float v01 = fmaxf(acc[f][1], 0.f) + tl.y;
            float v10 = fmaxf(acc[f][2], 0.f) + th.x;
            float v11 = fmaxf(acc[f][3], 0.f) + th.y;
            if (!((mb >> (f * 4 + 0)) & 1u)) v00 = 0.f;
            if (!((mb >> (f * 4 + 1)) & 1u)) v01 = 0.f;
            if (!((mb >> (f * 4 + 2)) & 1u)) v10 = 0.f;
            if (!((mb >> (f * 4 + 3)) & 1u)) v11 = 0.f;
            *(__half2*)(g_b2h + (size_t)r0 * CCH + c0) = __floats2half2_rn(v00, v01);
            *(__half2*)(g_b2h + (size_t)(r0 + 8) * CCH + c0) = __floats2half2_rn(v10, v11);
        }
        __syncthreads();   // A buffers reused next iteration
    }
}

// ---------------- K2: dw2(b2h) -> gemm W3 -> relu -> g_b2ph ------------------
__global__ void __launch_bounds__(NT)
K2(const float* __restrict__ wdw) {
    extern __shared__ char sm[];
    char* W3h = sm;
    char* W3l = sm + WBYTES;
    char* A   = sm + 2 * WBYTES;
    float* taps = (float*)(sm + 3 * WBYTES);

    const int tid = threadIdx.x, lane = tid & 31, warp = tid >> 5;
    const int m0 = (warp & 3) * 32, c0w = (warp >> 2) * 32;
    const int g = lane >> 2, t = lane & 3;

    loadW(W3h, W3l, 2, tid);
    for (int e = tid; e < 3 * CCH; e += NT)
        taps[e] = wdw[(e & 127) * 9 + (e >> 7) * 3 + 1];

    const u32 as = smem_u32(A);
    const u32 whs = smem_u32(W3h), wls = smem_u32(W3l);

    for (int tile = blockIdx.x; tile < NTILES; tile += gridDim.x) {
        const int base = tile * TILE_M;
        fillA_h(A, g_b2h, base, taps, tid);
        __syncthreads();

        float acc[8][4];
        ZACC(acc);
        sweep(as, whs, wls, m0, c0w, lane, acc);

#pragma unroll
        for (int f = 0; f < 8; f++) {
            const int mt = f >> 2, nt = f & 3;
            const int r0 = base + m0 + mt * 16 + g;
            const int c0 = c0w + nt * 8 + t * 2;
            *(__half2*)(g_b2ph + (size_t)r0 * CCH + c0) =
                __floats2half2_rn(fmaxf(acc[f][0], 0.f), fmaxf(acc[f][1], 0.f));
            *(__half2*)(g_b2ph + (size_t)(r0 + 8) * CCH + c0) =
                __floats2half2_rn(fmaxf(acc[f][2], 0.f), fmaxf(acc[f][3], 0.f));
        }
        __syncthreads();
    }
}

// ---------------- K3: out = relu(xh @ Wfa^T + b2ph @ Wfb^T), pipelined -------
__device__ __forceinline__ void prefK3(uint4 pfx[4], uint4 pfb[4],
                                       int base, int tid) {
#pragma unroll
    for (int c = 0; c < 4; c++) {
        int q = tid + c * NT;
        int m = q >> 4, k0 = (q & 15) << 3;
        size_t go = (size_t)(base + m) * CCH + k0;
        pfx[c] = *(const uint4*)(g_xh + go);
        pfb[c] = *(const uint4*)(g_b2ph + go);
    }
}

__global__ void __launch_bounds__(NT)
K3(float* __restrict__ out) {
    extern __shared__ char sm[];
    char* Wah = sm;
    char* Wal = sm + WBYTES;
    char* Wbh = sm + 2 * WBYTES;
    char* Wbl = sm + 3 * WBYTES;
    char* A0  = sm + 4 * WBYTES;
    char* A1  = sm + 5 * WBYTES;

    const int tid = threadIdx.x, lane = tid & 31, warp = tid >> 5;
    const int m0 = (warp & 3) * 32, c0w = (warp >> 2) * 32;
    const int g = lane >> 2, t = lane & 3;

    loadW(Wah, Wal, 3, tid);
    loadW(Wbh, Wbl, 4, tid);

    const u32 a0s = smem_u32(A0), a1s = smem_u32(A1);
    const u32 wahs = smem_u32(Wah), wals = smem_u32(Wal);
    const u32 wbhs = smem_u32(Wbh), wbls = smem_u32(Wbl);

    uint4 pfx[4], pfb[4];
    int tile = blockIdx.x;
    if (tile < NTILES) prefK3(pfx, pfb, tile * TILE_M, tid);

    for (; tile < NTILES; tile += gridDim.x) {
#pragma unroll
        for (int c = 0; c < 4; c++) {
            int q = tid + c * NT;
            int m = q >> 4, k0 = (q & 15) << 3;
            u32 off = (u32)(m * PITCHB + k0) * 2;
            *(uint4*)(A0 + off) = pfx[c];
            *(uint4*)(A1 + off) = pfb[c];
        }
        __syncthreads();

        int ntile = tile + gridDim.x;
        if (ntile < NTILES) prefK3(pfx, pfb, ntile * TILE_M, tid);

        float acc[8][4];
        ZACC(acc);
        sweep_dual(a0s, a1s, wahs, wals, wbhs, wbls, m0, c0w, lane, acc);

        const int base = tile * TILE_M;
#pragma unroll
        for (int f = 0; f < 8; f++) {
            const int mt = f >> 2, nt = f & 3;
            const int r0 = base + m0 + mt * 16 + g;
            const int c0 = c0w + nt * 8 + t * 2;
            *(float2*)(out + (size_t)r0 * CCH + c0) =
                make_float2(fmaxf(acc[f][0], 0.f), fmaxf(acc[f][1], 0.f));
            *(float2*)(out + (size_t)(r0 + 8) * CCH + c0) =
                make_float2(fmaxf(acc[f][2], 0.f), fmaxf(acc[f][3], 0.f));
        }
        __syncthreads();
    }
}

// ---------------- launch ------------------------------------------------------
extern "C" void kernel_launch(void* const* d_in, const int* in_sizes, int n_in,
                              void* d_out, int out_size) {
    const float* x        = (const float*)d_in[0];
    const float* w_b1_dw  = (const float*)d_in[1];
    const float* w_b1_pw  = (const float*)d_in[2];
    const float* w_b2_1x1 = (const float*)d_in[3];
    const float* w_b2_dw  = (const float*)d_in[4];
    const float* w_b2_pw  = (const float*)d_in[5];
    const float* w_fusion = (const float*)d_in[6];
    float*       out      = (float*)d_out;

    cudaFuncSetAttribute(K1, cudaFuncAttributeMaxDynamicSharedMemorySize, SM1);
    cudaFuncSetAttribute(K2, cudaFuncAttributeMaxDynamicSharedMemorySize, SM2);
    cudaFuncSetAttribute(K3, cudaFuncAttributeMaxDynamicSharedMemorySize, SM3);

    kPrep<<<(5 * CCH * CCH + 255) / 256, 256>>>(w_b1_pw, w_b2_1x1, w_b2_pw, w_fusion);
    K1<<<GRID1, NT, SM1>>>(x, w_b1_dw);
    K2<<<GRID2, NT, SM2>>>(w_b2_dw);
    K3<<<GRID1, NT, SM3>>>(out);
}

// round 16
// speedup vs baseline: 1.0715x; 1.0715x over previous
#include <cuda_runtime.h>
#include <cuda_fp16.h>

// ----------------------------------------------------------------------------
// KB_Mapping_19361712570541 — HMMA fp16 2-term split, persistent CTAs,
// fp16 intermediates, prefetch pipelines (incl. halo), mask fused in sweep,
// K1 reordered for pipe mixing, dw in half2.
//   K1: A1 = fp16(x); accX = A1@W2 (+mask); A0 = relu(dw1(A1)) [half2];
//       accT = A0@W1; b2 = mask(relu X) + mask(relu T) -> g_b2h; writes g_xh.
//   K2: b2p = relu(relu(dw2(b2h)) @ W3^T) -> g_b2ph
//   K3: out = relu(xh @ Wfa^T + b2ph @ Wfb^T)
// GEMMs: A@W ~= Afp16 @ Whi + Afp16 @ Wlo  (W split ~22 mantissa bits).
// Warp map (16 warps, 4x4): rows (warp&3)*32..+32, cols (warp>>2)*32..+32.
// ----------------------------------------------------------------------------

#define NTOK   131072
#define CCH    128
#define TILE_M 128
#define NTILES (NTOK / TILE_M)   // 1024
#define NT     512
#define PITCHB 136               // fp16 smem pitch (ldmatrix conflict-free)
#define WBYTES (CCH * PITCHB * 2)   // 34816 bytes per fp16 matrix tile
#define GRID1  148
#define GRID2  296

typedef unsigned int u32;

// ---------------- device scratch ---------------------------------------------
__device__ __half g_xh  [(size_t)NTOK * CCH];   // fp16(x), written by K1
__device__ __half g_b2h [(size_t)NTOK * CCH];   // fp16(b2)
__device__ __half g_b2ph[(size_t)NTOK * CCH];   // fp16(b2p)
__device__ __half g_whi[5][CCH * CCH];          // row-major [o][k] hi part
__device__ __half g_wlo[5][CCH * CCH];          // lo part (residual)

// ---------------- PTX helpers -------------------------------------------------
__device__ __forceinline__ u32 smem_u32(const void* p) {
    u32 a;
    asm("{ .reg .u64 t; cvta.to.shared.u64 t, %1; cvt.u32.u64 %0, t; }"
        : "=r"(a) : "l"(p));
    return a;
}
#define LDM4(r, a)                                                          \
    asm volatile("ldmatrix.sync.aligned.m8n8.x4.shared.b16 {%0,%1,%2,%3}, [%4];" \
                 : "=r"((r)[0]), "=r"((r)[1]), "=r"((r)[2]), "=r"((r)[3])   \
                 : "r"(a))
#define MMA(c, a, b0, b1)                                                   \
    asm volatile("mma.sync.aligned.m16n8k16.row.col.f32.f16.f16.f32 "       \
                 "{%0,%1,%2,%3}, {%4,%5,%6,%7}, {%8,%9}, {%0,%1,%2,%3};"    \
                 : "+f"((c)[0]), "+f"((c)[1]), "+f"((c)[2]), "+f"((c)[3])   \
                 : "r"((a)[0]), "r"((a)[1]), "r"((a)[2]), "r"((a)[3]),      \
                   "r"(b0), "r"(b1))

// ---------------- threefry-2x32 partitionable keep-bit (validated R5) ---------
__device__ __forceinline__ u32 rotl32(u32 x, int r) { return __funnelshift_l(x, x, r); }
__device__ __forceinline__ u32 keepbit(u32 fidx) {
    const u32 K0 = 0u, K1 = 42u, K2 = 0u ^ 42u ^ 0x1BD11BDAu;
    u32 x0 = 0u + K0;      // counts_hi = 0
    u32 x1 = fidx + K1;    // counts_lo = f
#define TF_R4(a,b,c,d)                               \
    x0 += x1; x1 = rotl32(x1,(a)); x1 ^= x0;         \
    x0 += x1; x1 = rotl32(x1,(b)); x1 ^= x0;         \
    x0 += x1; x1 = rotl32(x1,(c)); x1 ^= x0;         \
    x0 += x1; x1 = rotl32(x1,(d)); x1 ^= x0;
    TF_R4(13,15,26, 6);  x0 += K1; x1 += K2 + 1u;
    TF_R4(17,29,16,24);  x0 += K2; x1 += K0 + 2u;
    TF_R4(13,15,26, 6);  x0 += K0; x1 += K1 + 3u;
    TF_R4(17,29,16,24);  x0 += K1; x1 += K2 + 4u;
    TF_R4(13,15,26, 6);  x0 += K2; x1 += K0 + 5u;
#undef TF_R4
    return (~(x0 ^ x1)) >> 31;   // 1 = keep (MSB of xor-fold == 0)
}

// ---------------- weight prep: fp16 hi/lo split, row-major [o][k] ------------
__global__ void kPrep(const float* __restrict__ w1, const float* __restrict__ w2,
                      const float* __restrict__ w3, const float* __restrict__ wf) {
    int e = blockIdx.x * blockDim.x + threadIdx.x;
    if (e >= 5 * CCH * CCH) return;
    int mat = e >> 14, idx = e & 16383, o = idx >> 7, k = idx & 127;
    float v;
    if      (mat == 0) v = w1[idx];              // w_b1_pw
    else if (mat == 1) v = w2[idx];              // w_b2_1x1
    else if (mat == 2) v = w3[idx];              // w_b2_pw
    else if (mat == 3) v = wf[o * 256 + k];      // w_fusion[:, :128]
    else               v = wf[o * 256 + 128 + k];// w_fusion[:, 128:]
    __half h = __float2half_rn(v);
    __half l = __float2half_rn(v - __half2float(h));
    g_whi[mat][idx] = h;
    g_wlo[mat][idx] = l;
}

// ---------------- tile helpers ------------------------------------------------
__device__ __forceinline__ void load8(float v[8], const float* __restrict__ p,
                                      long row, int k0) {
    if ((unsigned long)row < (unsigned long)NTOK) {
        float4 a = *(const float4*)(p + row * CCH + k0);
        float4 b = *(const float4*)(p + row * CCH + k0 + 4);
        v[0]=a.x; v[1]=a.y; v[2]=a.z; v[3]=a.w;
        v[4]=b.x; v[5]=b.y; v[6]=b.z; v[7]=b.w;
    } else {
#pragma unroll
        for (int j = 0; j < 8; j++) v[j] = 0.f;
    }
}
__device__ __forceinline__ void load8h(float v[8], const __half* __restrict__ p,
                                       long row, int k0) {
    if ((unsigned long)row < (unsigned long)NTOK) {
        uint4 r = *(const uint4*)(p + row * CCH + k0);
        const __half2* h2 = (const __half2*)&r;
#pragma unroll
        for (int j = 0; j < 4; j++) {
            float2 f = __half22float2(h2[j]);
            v[2 * j] = f.x; v[2 * j + 1] = f.y;
        }
    } else {
#pragma unroll
        for (int j = 0; j < 8; j++) v[j] = 0.f;
    }
}
__device__ __forceinline__ uint4 pack8h(const float v[8]) {
    uint4 r;
    __half2* h2 = (__half2*)&r;
#pragma unroll
    for (int j = 0; j < 4; j++)
        h2[j] = __floats2half2_rn(v[2 * j], v[2 * j + 1]);
    return r;
}

// Copy one pre-split weight matrix into pitched smem (hi+lo).
__device__ __forceinline__ void loadW(char* hd, char* ld, int mat, int tid) {
    const uint4* sh = (const uint4*)g_whi[mat];
    const uint4* sl = (const uint4*)g_wlo[mat];
#pragma unroll
    for (int q = tid; q < 2048; q += NT) {             // 16 uint4 per row
        int n = q >> 4, k0 = (q & 15) << 3;
        u32 doff = (u32)(n * PITCHB + k0) * 2;
        *(uint4*)(hd + doff) = sh[q];
        *(uint4*)(ld + doff) = sl[q];
    }
}

// K2 fill from fp16 source with fused dw + relu (fp32 math).
__device__ __forceinline__ void fillA_h(char* A, const __half* __restrict__ src,
                                        int base, const float* taps, int tid) {
#pragma unroll 1
    for (int q = tid; q < 2048; q += NT) {
        int m = q >> 4, k0 = (q & 15) << 3;
        long gr = (long)base + m;
        float a[8], b[8], c[8], v[8];
        load8h(a, src, gr - 1, k0);
        load8h(b, src, gr,     k0);
        load8h(c, src, gr + 1, k0);
#pragma unroll
        for (int j = 0; j < 8; j++) {
            int ch = k0 + j;
            v[j] = fmaxf(taps[ch] * a[j] + taps[CCH + ch] * b[j]
                         + taps[2 * CCH + ch] * c[j], 0.f);
        }
        *(uint4*)(A + (u32)(m * PITCHB + k0) * 2) = pack8h(v);
    }
}

// 2-term split GEMM sweep: acc += A @ Whi + A @ Wlo.
// Warp: rows [m0, m0+32) (2 m-tiles) x cols [c0w, c0w+32) (2 n-pairs).
__device__ __forceinline__ void sweep(u32 as, u32 whs, u32 wls,
                                      int m0, int c0w, int lane, float (*acc)[4]) {
    const u32 arow  = (u32)(m0 + (lane & 7) + (lane & 8));
    const u32 acolb = (u32)((lane & 16) >> 1);             // 0 or 8
    const u32 brow0 = (u32)((lane & 7) + ((lane & 16) >> 1));
    const u32 astride = (u32)(16 * PITCHB * 2);            // 16 rows of A
#pragma unroll 2
    for (int k = 0; k < 8; k++) {
        u32 aoff = (arow * PITCHB + (u32)k * 16 + acolb) * 2;
        u32 a0[4], a1[4];
        LDM4(a0, as + aoff);
        LDM4(a1, as + aoff + astride);
        u32 bcol = ((u32)k * 16 + (u32)(lane & 8)) * 2;
        u32 boff0 = ((u32)c0w        + brow0) * (PITCHB * 2) + bcol;
        u32 boff1 = ((u32)(c0w + 16) + brow0) * (PITCHB * 2) + bcol;
        u32 bh0[4], bl0[4], bh1[4], bl1[4];
        LDM4(bh0, whs + boff0);
        LDM4(bl0, wls + boff0);
        LDM4(bh1, whs + boff1);
        LDM4(bl1, wls + boff1);
        MMA(acc[0], a0, bh0[0], bh0[1]);
        MMA(acc[0], a0, bl0[0], bl0[1]);
        MMA(acc[1], a0, bh0[2], bh0[3]);
        MMA(acc[1], a0, bl0[2], bl0[3]);
        MMA(acc[2], a0, bh1[0], bh1[1]);
        MMA(acc[2], a0, bl1[0], bl1[1]);
        MMA(acc[3], a0, bh1[2], bh1[3]);
        MMA(acc[3], a0, bl1[2], bl1[3]);
        MMA(acc[4], a1, bh0[0], bh0[1]);
        MMA(acc[4], a1, bl0[0], bl0[1]);
        MMA(acc[5], a1, bh0[2], bh0[3]);
        MMA(acc[5], a1, bl0[2], bl0[3]);
        MMA(acc[6], a1, bh1[0], bh1[1]);
        MMA(acc[6], a1, bl1[0], bl1[1]);
        MMA(acc[7], a1, bh1[2], bh1[3]);
        MMA(acc[7], a1, bl1[2], bl1[3]);
    }
}

// Sweep variant with threefry mask fused into the k-loop: iteration k also
// computes the 4 keep-bits of output fragment k (rides idle issue slots).
__device__ __forceinline__ void sweep_mask(u32 as, u32 whs, u32 wls,
                                           int m0, int c0w, int lane,
                                           int base, int g, int t,
                                           float (*acc)[4], u32* mbout) {
    const u32 arow  = (u32)(m0 + (lane & 7) + (lane & 8));
    const u32 acolb = (u32)((lane & 16) >> 1);
    const u32 brow0 = (u32)((lane & 7) + ((lane & 16) >> 1));
    const u32 astride = (u32)(16 * PITCHB * 2);
    u32 mb = 0;
#pragma unroll 2
    for (int k = 0; k < 8; k++) {
        u32 aoff = (arow * PITCHB + (u32)k * 16 + acolb) * 2;
        u32 a0[4], a1[4];
        LDM4(a0, as + aoff);
        LDM4(a1, as + aoff + astride);
        u32 bcol = ((u32)k * 16 + (u32)(lane & 8)) * 2;
        u32 boff0 = ((u32)c0w        + brow0) * (PITCHB * 2) + bcol;
        u32 boff1 = ((u32)(c0w + 16) + brow0) * (PITCHB * 2) + bcol;
        u32 bh0[4], bl0[4], bh1[4], bl1[4];
        LDM4(bh0, whs + boff0);
        LDM4(bl0, wls + boff0);
        LDM4(bh1, whs + boff1);
        LDM4(bl1, wls + boff1);
        MMA(acc[0], a0, bh0[0], bh0[1]);
        MMA(acc[0], a0, bl0[0], bl0[1]);
        MMA(acc[1], a0, bh0[2], bh0[3]);
        MMA(acc[1], a0, bl0[2], bl0[3]);
        MMA(acc[2], a0, bh1[0], bh1[1]);
        MMA(acc[2], a0, bl1[0], bl1[1]);
        MMA(acc[3], a0, bh1[2], bh1[3]);
        MMA(acc[3], a0, bl1[2], bl1[3]);
        MMA(acc[4], a1, bh0[0], bh0[1]);
        MMA(acc[4], a1, bl0[0], bl0[1]);
        MMA(acc[5], a1, bh0[2], bh0[3]);
        MMA(acc[5], a1, bl0[2], bl0[3]);
        MMA(acc[6], a1, bh1[0], bh1[1]);
        MMA(acc[6], a1, bl1[0], bl1[1]);
        MMA(acc[7], a1, bh1[2], bh1[3]);
        MMA(acc[7], a1, bl1[2], bl1[3]);
        // fragment k mask bits: flat index = col*131072 + row
        {
            u32 r0 = (u32)(base + m0 + (k >> 2) * 16 + g);
            u32 c0 = (u32)(c0w + (k & 3) * 8 + t * 2);
            u32 fb = (c0 << 17) + r0;
            mb |= keepbit(fb)                    << (k * 4 + 0);
            mb |= keepbit(fb + (1u << 17))       << (k * 4 + 1);
            mb |= keepbit(fb + 8u)               << (k * 4 + 2);
            mb |= keepbit(fb + (1u << 17) + 8u)  << (k * 4 + 3);
        }
    }
    *mbout = mb;
}

#define ZACC(a) { _Pragma("unroll") for (int _i = 0; _i < 8; _i++) \
                  _Pragma("unroll") for (int _j = 0; _j < 4; _j++) (a)[_i][_j] = 0.f; }

// Shared-memory sizes
#define SM1 (6 * WBYTES + 1024 + 4 * PITCHB)   // W1h/l W2h/l A0 A1, taps_h2, halo
#define SM2 (3 * WBYTES + 3 * CCH * 4)         // W3 h/l, A, taps
#define SM3 (6 * WBYTES)                       // Wfa h/l, Wfb h/l, A0, A1

// ---------------- K1 ----------------------------------------------------------
// Prefetch next tile's x rows (fp32) + halo rows (tid<32).
__device__ __forceinline__ void prefK1(uint4 pf[4][2], uint4 pfh[2],
                                       const float* __restrict__ x,
                                       int base, int tid) {
#pragma unroll
    for (int c = 0; c < 4; c++) {
        int q = tid + c * NT;
        int m = q >> 4, k0 = (q & 15) << 3;
        const float* p = x + (size_t)(base + m) * CCH + k0;
        pf[c][0] = *(const uint4*)p;
        pf[c][1] = *(const uint4*)(p + 4);
    }
    if (tid < 32) {
        int sel = tid >> 4;              // 0: base-1, 1: base+TILE_M
        int k0 = (tid & 15) << 3;
        long gr = sel ? (long)base + TILE_M : (long)base - 1;
        if ((unsigned long)gr < (unsigned long)NTOK) {
            const float* p = x + gr * CCH + k0;
            pfh[0] = *(const uint4*)p;
            pfh[1] = *(const uint4*)(p + 4);
        } else {
            pfh[0] = make_uint4(0, 0, 0, 0);
            pfh[1] = make_uint4(0, 0, 0, 0);
        }
    }
}

__global__ void __launch_bounds__(NT)
K1(const float* __restrict__ x, const float* __restrict__ wdw) {
    extern __shared__ char sm[];
    char* W1h = sm;
    char* W1l = sm + WBYTES;
    char* W2h = sm + 2 * WBYTES;
    char* W2l = sm + 3 * WBYTES;
    char* A0  = sm + 4 * WBYTES;
    char* A1  = sm + 5 * WBYTES;
    __half2* tap2 = (__half2*)(sm + 6 * WBYTES);       // [3][64] half2 pairs
    char* haloH = sm + 6 * WBYTES + 1024;              // 2 rows x PITCHB fp16

    const int tid = threadIdx.x, lane = tid & 31, warp = tid >> 5;
    const int m0 = (warp & 3) * 32, c0w = (warp >> 2) * 32;
    const int g = lane >> 2, t = lane & 3;

    loadW(W1h, W1l, 0, tid);
    loadW(W2h, W2l, 1, tid);
    // taps as half2 channel-pairs: tap2[k*64 + cp] = (tap[2cp], tap[2cp+1])
    for (int e = tid; e < 3 * 64; e += NT) {
        int k = e >> 6, cp = e & 63, ch = cp * 2;
        tap2[e] = __floats2half2_rn(wdw[ch * 9 + k * 3 + 1],
                                    wdw[(ch + 1) * 9 + k * 3 + 1]);
    }

    const u32 a0s = smem_u32(A0), a1s = smem_u32(A1);
    const u32 w1hs = smem_u32(W1h), w1ls = smem_u32(W1l);
    const u32 w2hs = smem_u32(W2h), w2ls = smem_u32(W2l);
    const __half2 z2 = __float2half2_rn(0.f);

    uint4 pf[4][2], pfh[2];
    int tile = blockIdx.x;
    if (tile < NTILES) prefK1(pf, pfh, x, tile * TILE_M, tid);

    for (; tile < NTILES; tile += gridDim.x) {
        const int base = tile * TILE_M;

        // stage A1 = fp16(x) from prefetch; side-write g_xh; halo from prefetch
#pragma unroll
        for (int c = 0; c < 4; c++) {
            int q = tid + c * NT;
            int m = q >> 4, k0 = (q & 15) << 3;
            uint4 hx = pack8h((const float*)pf[c]);
            *(uint4*)(A1 + (u32)(m * PITCHB + k0) * 2) = hx;
            *(uint4*)(g_xh + (size_t)(base + m) * CCH + k0) = hx;
        }
        if (tid < 32) {
            int sel = tid >> 4, k0 = (tid & 15) << 3;
            *(uint4*)(haloH + (u32)(sel * PITCHB + k0) * 2) =
                pack8h((const float*)pfh);
        }
        __syncthreads();

        // accX = x @ W2^T with fused threefry mask
        float acc[8][4];
        ZACC(acc);
        u32 mb;
        sweep_mask(a1s, w2hs, w2ls, m0, c0w, lane, base, g, t, acc, &mb);

        // compress mask.relu(accX) to 16 fp16x2 regs (frees accX)
        u32 cX[16];
#pragma unroll
        for (int f = 0; f < 8; f++) {
            float v00 = ((mb >> (f * 4 + 0)) & 1u) ? fmaxf(acc[f][0], 0.f) : 0.f;
            float v01 = ((mb >> (f * 4 + 1)) & 1u) ? fmaxf(acc[f][1], 0.f) : 0.f;
            float v10 = ((mb >> (f * 4 + 2)) & 1u) ? fmaxf(acc[f][2], 0.f) : 0.f;
            float v11 = ((mb >> (f * 4 + 3)) & 1u) ? fmaxf(acc[f][3], 0.f) : 0.f;
            __half2 lo = __floats2half2_rn(v00, v01);
            __half2 hi = __floats2half2_rn(v10, v11);
            cX[2 * f]     = *(u32*)&lo;
            cX[2 * f + 1] = *(u32*)&hi;
        }

        // A0 = fp16(relu(dw1(A1)))  — half2 arithmetic, all-smem reads
#pragma unroll 1
        for (int c = 0; c < 4; c++) {
            int q = tid + c * NT;
            int m = q >> 4, k0 = (q & 15) << 3;
            u32 offm = (u32)(m * PITCHB + k0) * 2;
            uint4 rm = (m == 0)
                ? *(const uint4*)(haloH + (u32)k0 * 2)
                : *(const uint4*)(A1 + offm - PITCHB * 2);
            uint4 md = *(const uint4*)(A1 + offm);
            uint4 rp = (m == TILE_M - 1)
                ? *(const uint4*)(haloH + (u32)(PITCHB + k0) * 2)
                : *(const uint4*)(A1 + offm + PITCHB * 2);
            uint4 t0v = *(const uint4*)(tap2 + (k0 >> 1));
            uint4 t1v = *(const uint4*)(tap2 + 64 + (k0 >> 1));
            uint4 t2v = *(const uint4*)(tap2 + 128 + (k0 >> 1));
            uint4 o;
            const __half2* ap = (const __half2*)&rm;
            const __half2* bp = (const __half2*)&md;
            const __half2* cp = (const __half2*)&rp;
            const __half2* t0p = (const __half2*)&t0v;
            const __half2* t1p = (const __half2*)&t1v;
            const __half2* t2p = (const __half2*)&t2v;
            __half2* op = (__half2*)&o;
#pragma unroll
            for (int j = 0; j < 4; j++) {
                __half2 r = __hmul2(t0p[j], ap[j]);
                r = __hfma2(t1p[j], bp[j], r);
                r = __hfma2(t2p[j], cp[j], r);
                op[j] = __hmax2(r, z2);
            }
            *(uint4*)(A0 + offm) = o;
        }

        // issue next tile's loads (incl. halo); they fly during sweep1
        int ntile = tile + gridDim.x;
        if (ntile < NTILES) prefK1(pf, pfh, x, ntile * TILE_M, tid);
        __syncthreads();   // A0 complete

        // accT = relu(dw1(x)) @ W1^T
        ZACC(acc);
        sweep(a0s, w1hs, w1ls, m0, c0w, lane, acc);

        // b2 = mask.relu(X) + mask.relu(T) -> g_b2h (fp16)
#pragma unroll
        for (int f = 0; f < 8; f++) {
            const int mt = f >> 2, nt = f & 3;
            const int r0 = base + m0 + mt * 16 + g;
            const int c0 = c0w + nt * 8 + t * 2;
            float2 cxl = __half22float2(*(__half2*)&cX[2 * f]);
            float2 cxh = __half22float2(*(__half2*)&cX[2 * f + 1]);
            float v00 = cxl.x, v01 = cxl.y, v10 = cxh.x, v11 = cxh.y;
            if ((mb >> (f * 4 + 0)) & 1u) v00 += fmaxf(acc[f][0], 0.f);
            if ((mb >> (f * 4 + 1)) & 1u) v01 += fmaxf(acc[f][1], 0.f);
            if ((mb >> (f * 4 + 2)) & 1u) v10 += fmaxf(acc[f][2], 0.f);
            if ((mb >> (f * 4 + 3)) & 1u) v11 += fmaxf(acc[f][3], 0.f);
            *(__half2*)(g_b2h + (size_t)r0 * CCH + c0) = __floats2half2_rn(v00, v01);
            *(__half2*)(g_b2h + (size_t)(r0 + 8) * CCH + c0) = __floats2half2_rn(v10, v11);
        }
        // next stage writes A1 only after this bar-less region; safety: A1's
        // last read was dw (before the barrier above); stage is post-loop-wrap.
    }
}

// ---------------- K2: dw2(b2h) -> gemm W3 -> relu -> g_b2ph ------------------
__global__ void __launch_bounds__(NT)
K2(const float* __restrict__ wdw) {
    extern __shared__ char sm[];
    char* W3h = sm;
    char* W3l = sm + WBYTES;
    char* A   = sm + 2 * WBYTES;
    float* taps = (float*)(sm + 3 * WBYTES);

    const int tid = threadIdx.x, lane = tid & 31, warp = tid >> 5;
    const int m0 = (warp & 3) * 32, c0w = (warp >> 2) * 32;
    const int g = lane >> 2, t = lane & 3;

    loadW(W3h, W3l, 2, tid);
    for (int e = tid; e < 3 * CCH; e += NT)
        taps[e] = wdw[(e & 127) * 9 + (e >> 7) * 3 + 1];

    const u32 as = smem_u32(A);
    const u32 whs = smem_u32(W3h), wls = smem_u32(W3l);

    for (int tile = blockIdx.x; tile < NTILES; tile += gridDim.x) {
        const int base = tile * TILE_M;
        fillA_h(A, g_b2h, base, taps, tid);
        __syncthreads();

        float acc[8][4];
        ZACC(acc);
        sweep(as, whs, wls, m0, c0w, lane, acc);

#pragma unroll
        for (int f = 0; f < 8; f++) {
            const int mt = f >> 2, nt = f & 3;
            const int r0 = base + m0 + mt * 16 + g;
            const int c0 = c0w + nt * 8 + t * 2;
            *(__half2*)(g_b2ph + (size_t)r0 * CCH + c0) =
                __floats2half2_rn(fmaxf(acc[f][0], 0.f), fmaxf(acc[f][1], 0.f));
            *(__half2*)(g_b2ph + (size_t)(r0 + 8) * CCH + c0) =
                __floats2half2_rn(fmaxf(acc[f][2], 0.f), fmaxf(acc[f][3], 0.f));
        }
        __syncthreads();
    }
}

// ---------------- K3: out = relu(xh @ Wfa^T + b2ph @ Wfb^T), pipelined -------
__device__ __forceinline__ void prefK3(uint4 pfx[4], uint4 pfb[4],
                                       int base, int tid) {
#pragma unroll
    for (int c = 0; c < 4; c++) {
        int q = tid + c * NT;
        int m = q >> 4, k0 = (q & 15) << 3;
        size_t go = (size_t)(base + m) * CCH + k0;
        pfx[c] = *(const uint4*)(g_xh + go);
        pfb[c] = *(const uint4*)(g_b2ph + go);
    }
}

__global__ void __launch_bounds__(NT)
K3(float* __restrict__ out) {
    extern __shared__ char sm[];
    char* Wah = sm;
    char* Wal = sm + WBYTES;
    char* Wbh = sm + 2 * WBYTES;
    char* Wbl = sm + 3 * WBYTES;
    char* A0  = sm + 4 * WBYTES;
    char* A1  = sm + 5 * WBYTES;

    const int tid = threadIdx.x, lane = tid & 31, warp = tid >> 5;
    const int m0 = (warp & 3) * 32, c0w = (warp >> 2) * 32;
    const int g = lane >> 2, t = lane & 3;

    loadW(Wah, Wal, 3, tid);
    loadW(Wbh, Wbl, 4, tid);

    const u32 a0s = smem_u32(A0), a1s = smem_u32(A1);
    const u32 wahs = smem_u32(Wah), wals = smem_u32(Wal);
    const u32 wbhs = smem_u32(Wbh), wbls = smem_u32(Wbl);

    uint4 pfx[4], pfb[4];
    int tile = blockIdx.x;
    if (tile < NTILES) prefK3(pfx, pfb, tile * TILE_M, tid);

    for (; tile < NTILES; tile += gridDim.x) {
#pragma unroll
        for (int c = 0; c < 4; c++) {
            int q = tid + c * NT;
            int m = q >> 4, k0 = (q & 15) << 3;
            u32 off = (u32)(m * PITCHB + k0) * 2;
            *(uint4*)(A0 + off) = pfx[c];
            *(uint4*)(A1 + off) = pfb[c];
        }
        __syncthreads();

        int ntile = tile + gridDim.x;
        if (ntile < NTILES) prefK3(pfx, pfb, ntile * TILE_M, tid);

        float acc[8][4];
        ZACC(acc);
        sweep(a0s, wahs, wals, m0, c0w, lane, acc);
        sweep(a1s, wbhs, wbls, m0, c0w, lane, acc);

        const int base = tile * TILE_M;
#pragma unroll
        for (int f = 0; f < 8; f++) {
            const int mt = f >> 2, nt = f & 3;
            const int r0 = base + m0 + mt * 16 + g;
            const int c0 = c0w + nt * 8 + t * 2;
            *(float2*)(out + (size_t)r0 * CCH + c0) =
                make_float2(fmaxf(acc[f][0], 0.f), fmaxf(acc[f][1], 0.f));
            *(float2*)(out + (size_t)(r0 + 8) * CCH + c0) =
                make_float2(fmaxf(acc[f][2], 0.f), fmaxf(acc[f][3], 0.f));
        }
        __syncthreads();
    }
}

// ---------------- launch ------------------------------------------------------
extern "C" void kernel_launch(void* const* d_in, const int* in_sizes, int n_in,
                              void* d_out, int out_size) {
    const float* x        = (const float*)d_in[0];
    const float* w_b1_dw  = (const float*)d_in[1];
    const float* w_b1_pw  = (const float*)d_in[2];
    const float* w_b2_1x1 = (const float*)d_in[3];
    const float* w_b2_dw  = (const float*)d_in[4];
    const float* w_b2_pw  = (const float*)d_in[5];
    const float* w_fusion = (const float*)d_in[6];
    float*       out      = (float*)d_out;

    cudaFuncSetAttribute(K1, cudaFuncAttributeMaxDynamicSharedMemorySize, SM1);
    cudaFuncSetAttribute(K2, cudaFuncAttributeMaxDynamicSharedMemorySize, SM2);
    cudaFuncSetAttribute(K3, cudaFuncAttributeMaxDynamicSharedMemorySize, SM3);

    kPrep<<<(5 * CCH * CCH + 255) / 256, 256>>>(w_b1_pw, w_b2_1x1, w_b2_pw, w_fusion);
    K1<<<GRID1, NT, SM1>>>(x, w_b1_dw);
    K2<<<GRID2, NT, SM2>>>(w_b2_dw);
    K3<<<GRID1, NT, SM3>>>(out);
}

// round 17
// speedup vs baseline: 1.0753x; 1.0035x over previous
#include <cuda_runtime.h>
#include <cuda_fp16.h>

// ----------------------------------------------------------------------------
// KB_Mapping_19361712570541 — HMMA fp16 2-term split, persistent CTAs.
//   K1 : A1 = fp16(x); accX = A1@W2 (+fused threefry mask);
//        A0 = relu(dw1(A1)) [half2]; accT = A0@W1;
//        b2 = mask.relu(X) + mask.relu(T) -> g_b2h; side-writes g_xh.
//   K23: fused b2p+fusion, b2p never hits DRAM:
//        A = relu(dw2(b2h)) ; acc1 = A@W3 ; A = fp16(relu(acc1)) [smem];
//        acc2 = A@Wfb ; A = xh (prefetched) ; acc2 += A@Wfa ;
//        out = relu(acc2).
// GEMMs: A@W ~= Afp16 @ Whi + Afp16 @ Wlo  (W split ~22 mantissa bits).
// K1 smem: pitch-136 fp16 (as validated). K23 smem: pitch-128 with XOR
// chunk swizzle (phys_chunk = chunk ^ (row&7)) to fit 7 tiles in 228KB.
// Warp map (16 warps, 4x4): rows (warp&3)*32..+32, cols (warp>>2)*32..+32.
// ----------------------------------------------------------------------------

#define NTOK   131072
#define CCH    128
#define TILE_M 128
#define NTILES (NTOK / TILE_M)   // 1024
#define NT     512
#define PITCHB 136               // K1 fp16 smem pitch (ldmatrix conflict-free)
#define WBYTES (CCH * PITCHB * 2)   // 34816 bytes per pitched tile (K1)
#define WSZ    32768             // K23 swizzled tile bytes (128 rows x 256B)
#define GRID1  148

typedef unsigned int u32;

// ---------------- device scratch ---------------------------------------------
__device__ __half g_xh  [(size_t)NTOK * CCH];   // fp16(x), written by K1
__device__ __half g_b2h [(size_t)NTOK * CCH];   // fp16(b2)
__device__ __half g_whi[5][CCH * CCH];          // row-major [o][k] hi part
__device__ __half g_wlo[5][CCH * CCH];          // lo part (residual)

// ---------------- PTX helpers -------------------------------------------------
__device__ __forceinline__ u32 smem_u32(const void* p) {
    u32 a;
    asm("{ .reg .u64 t; cvta.to.shared.u64 t, %1; cvt.u32.u64 %0, t; }"
        : "=r"(a) : "l"(p));
    return a;
}
#define LDM4(r, a)                                                          \
    asm volatile("ldmatrix.sync.aligned.m8n8.x4.shared.b16 {%0,%1,%2,%3}, [%4];" \
                 : "=r"((r)[0]), "=r"((r)[1]), "=r"((r)[2]), "=r"((r)[3])   \
                 : "r"(a))
#define MMA(c, a, b0, b1)                                                   \
    asm volatile("mma.sync.aligned.m16n8k16.row.col.f32.f16.f16.f32 "       \
                 "{%0,%1,%2,%3}, {%4,%5,%6,%7}, {%8,%9}, {%0,%1,%2,%3};"    \
                 : "+f"((c)[0]), "+f"((c)[1]), "+f"((c)[2]), "+f"((c)[3])   \
                 : "r"((a)[0]), "r"((a)[1]), "r"((a)[2]), "r"((a)[3]),      \
                   "r"(b0), "r"(b1))

// ---------------- threefry-2x32 partitionable keep-bit (validated R5) ---------
__device__ __forceinline__ u32 rotl32(u32 x, int r) { return __funnelshift_l(x, x, r); }
__device__ __forceinline__ u32 keepbit(u32 fidx) {
    const u32 K0 = 0u, K1 = 42u, K2 = 0u ^ 42u ^ 0x1BD11BDAu;
    u32 x0 = 0u + K0;      // counts_hi = 0
    u32 x1 = fidx + K1;    // counts_lo = f
#define TF_R4(a,b,c,d)                               \
    x0 += x1; x1 = rotl32(x1,(a)); x1 ^= x0;         \
    x0 += x1; x1 = rotl32(x1,(b)); x1 ^= x0;         \
    x0 += x1; x1 = rotl32(x1,(c)); x1 ^= x0;         \
    x0 += x1; x1 = rotl32(x1,(d)); x1 ^= x0;
    TF_R4(13,15,26, 6);  x0 += K1; x1 += K2 + 1u;
    TF_R4(17,29,16,24);  x0 += K2; x1 += K0 + 2u;
    TF_R4(13,15,26, 6);  x0 += K0; x1 += K1 + 3u;
    TF_R4(17,29,16,24);  x0 += K1; x1 += K2 + 4u;
    TF_R4(13,15,26, 6);  x0 += K2; x1 += K0 + 5u;
#undef TF_R4
    return (~(x0 ^ x1)) >> 31;   // 1 = keep (MSB of xor-fold == 0)
}

// ---------------- weight prep: fp16 hi/lo split, row-major [o][k] ------------
__global__ void kPrep(const float* __restrict__ w1, const float* __restrict__ w2,
                      const float* __restrict__ w3, const float* __restrict__ wf) {
    int e = blockIdx.x * blockDim.x + threadIdx.x;
    if (e >= 5 * CCH * CCH) return;
    int mat = e >> 14, idx = e & 16383, o = idx >> 7, k = idx & 127;
    float v;
    if      (mat == 0) v = w1[idx];              // w_b1_pw
    else if (mat == 1) v = w2[idx];              // w_b2_1x1
    else if (mat == 2) v = w3[idx];              // w_b2_pw
    else if (mat == 3) v = wf[o * 256 + k];      // w_fusion[:, :128]
    else               v = wf[o * 256 + 128 + k];// w_fusion[:, 128:]
    __half h = __float2half_rn(v);
    __half l = __float2half_rn(v - __half2float(h));
    g_whi[mat][idx] = h;
    g_wlo[mat][idx] = l;
}

// ---------------- tile helpers ------------------------------------------------
__device__ __forceinline__ void load8h(float v[8], const __half* __restrict__ p,
                                       long row, int k0) {
    if ((unsigned long)row < (unsigned long)NTOK) {
        uint4 r = *(const uint4*)(p + row * CCH + k0);
        const __half2* h2 = (const __half2*)&r;
#pragma unroll
        for (int j = 0; j < 4; j++) {
            float2 f = __half22float2(h2[j]);
            v[2 * j] = f.x; v[2 * j + 1] = f.y;
        }
    } else {
#pragma unroll
        for (int j = 0; j < 8; j++) v[j] = 0.f;
    }
}
__device__ __forceinline__ uint4 pack8h(const float v[8]) {
    uint4 r;
    __half2* h2 = (__half2*)&r;
#pragma unroll
    for (int j = 0; j < 4; j++)
        h2[j] = __floats2half2_rn(v[2 * j], v[2 * j + 1]);
    return r;
}

// K1 pitched weight copy.
__device__ __forceinline__ void loadW(char* hd, char* ld, int mat, int tid) {
    const uint4* sh = (const uint4*)g_whi[mat];
    const uint4* sl = (const uint4*)g_wlo[mat];
#pragma unroll
    for (int q = tid; q < 2048; q += NT) {
        int n = q >> 4, k0 = (q & 15) << 3;
        u32 doff = (u32)(n * PITCHB + k0) * 2;
        *(uint4*)(hd + doff) = sh[q];
        *(uint4*)(ld + doff) = sl[q];
    }
}

// K23 swizzled weight copy: row n, chunk cc -> phys chunk cc^(n&7).
__device__ __forceinline__ void loadW_sw(char* hd, char* ld, int mat, int tid) {
    const uint4* sh = (const uint4*)g_whi[mat];
    const uint4* sl = (const uint4*)g_wlo[mat];
#pragma unroll
    for (int q = tid; q < 2048; q += NT) {
        int n = q >> 4, cc = q & 15;
        u32 doff = (u32)(n * 256 + ((cc ^ (n & 7)) << 4));
        *(uint4*)(hd + doff) = sh[q];
        *(uint4*)(ld + doff) = sl[q];
    }
}

// ---------------- K1 sweeps (pitch-136, validated) ----------------------------
__device__ __forceinline__ void sweep(u32 as, u32 whs, u32 wls,
                                      int m0, int c0w, int lane, float (*acc)[4]) {
    const u32 arow  = (u32)(m0 + (lane & 7) + (lane & 8));
    const u32 acolb = (u32)((lane & 16) >> 1);
    const u32 brow0 = (u32)((lane & 7) + ((lane & 16) >> 1));
    const u32 astride = (u32)(16 * PITCHB * 2);
#pragma unroll 2
    for (int k = 0; k < 8; k++) {
        u32 aoff = (arow * PITCHB + (u32)k * 16 + acolb) * 2;
        u32 a0[4], a1[4];
        LDM4(a0, as + aoff);
        LDM4(a1, as + aoff + astride);
        u32 bcol = ((u32)k * 16 + (u32)(lane & 8)) * 2;
        u32 boff0 = ((u32)c0w        + brow0) * (PITCHB * 2) + bcol;
        u32 boff1 = ((u32)(c0w + 16) + brow0) * (PITCHB * 2) + bcol;
        u32 bh0[4], bl0[4], bh1[4], bl1[4];
        LDM4(bh0, whs + boff0);
        LDM4(bl0, wls + boff0);
        LDM4(bh1, whs + boff1);
        LDM4(bl1, wls + boff1);
        MMA(acc[0], a0, bh0[0], bh0[1]);
        MMA(acc[0], a0, bl0[0], bl0[1]);
        MMA(acc[1], a0, bh0[2], bh0[3]);
        MMA(acc[1], a0, bl0[2], bl0[3]);
        MMA(acc[2], a0, bh1[0], bh1[1]);
        MMA(acc[2], a0, bl1[0], bl1[1]);
        MMA(acc[3], a0, bh1[2], bh1[3]);
        MMA(acc[3], a0, bl1[2], bl1[3]);
        MMA(acc[4], a1, bh0[0], bh0[1]);
        MMA(acc[4], a1, bl0[0], bl0[1]);
        MMA(acc[5], a1, bh0[2], bh0[3]);
        MMA(acc[5], a1, bl0[2], bl0[3]);
        MMA(acc[6], a1, bh1[0], bh1[1]);
        MMA(acc[6], a1, bl1[0], bl1[1]);
        MMA(acc[7], a1, bh1[2], bh1[3]);
        MMA(acc[7], a1, bl1[2], bl1[3]);
    }
}

__device__ __forceinline__ void sweep_mask(u32 as, u32 whs, u32 wls,
                                           int m0, int c0w, int lane,
                                           int base, int g, int t,
                                           float (*acc)[4], u32* mbout) {
    const u32 arow  = (u32)(m0 + (lane & 7) + (lane & 8));
    const u32 acolb = (u32)((lane & 16) >> 1);
    const u32 brow0 = (u32)((lane & 7) + ((lane & 16) >> 1));
    const u32 astride = (u32)(16 * PITCHB * 2);
    u32 mb = 0;
#pragma unroll 2
    for (int k = 0; k < 8; k++) {
        u32 aoff = (arow * PITCHB + (u32)k * 16 + acolb) * 2;
        u32 a0[4], a1[4];
        LDM4(a0, as + aoff);
        LDM4(a1, as + aoff + astride);
        u32 bcol = ((u32)k * 16 + (u32)(lane & 8)) * 2;
        u32 boff0 = ((u32)c0w        + brow0) * (PITCHB * 2) + bcol;
        u32 boff1 = ((u32)(c0w + 16) + brow0) * (PITCHB * 2) + bcol;
        u32 bh0[4], bl0[4], bh1[4], bl1[4];
        LDM4(bh0, whs + boff0);
        LDM4(bl0, wls + boff0);
        LDM4(bh1, whs + boff1);
        LDM4(bl1, wls + boff1);
        MMA(acc[0], a0, bh0[0], bh0[1]);
        MMA(acc[0], a0, bl0[0], bl0[1]);
        MMA(acc[1], a0, bh0[2], bh0[3]);
        MMA(acc[1], a0, bl0[2], bl0[3]);
        MMA(acc[2], a0, bh1[0], bh1[1]);
        MMA(acc[2], a0, bl1[0], bl1[1]);
        MMA(acc[3], a0, bh1[2], bh1[3]);
        MMA(acc[3], a0, bl1[2], bl1[3]);
        MMA(acc[4], a1, bh0[0], bh0[1]);
        MMA(acc[4], a1, bl0[0], bl0[1]);
        MMA(acc[5], a1, bh0[2], bh0[3]);
        MMA(acc[5], a1, bl0[2], bl0[3]);
        MMA(acc[6], a1, bh1[0], bh1[1]);
        MMA(acc[6], a1, bl1[0], bl1[1]);
        MMA(acc[7], a1, bh1[2], bh1[3]);
        MMA(acc[7], a1, bl1[2], bl1[3]);
        {
            u32 r0 = (u32)(base + m0 + (k >> 2) * 16 + g);
            u32 c0 = (u32)(c0w + (k & 3) * 8 + t * 2);
            u32 fb = (c0 << 17) + r0;
            mb |= keepbit(fb)                    << (k * 4 + 0);
            mb |= keepbit(fb + (1u << 17))       << (k * 4 + 1);
            mb |= keepbit(fb + 8u)               << (k * 4 + 2);
            mb |= keepbit(fb + (1u << 17) + 8u)  << (k * 4 + 3);
        }
    }
    *mbout = mb;
}

// ---------------- K23 swizzled sweep (pitch-128, chunk^row&7) -----------------
__device__ __forceinline__ void sweep_sw(u32 as, u32 whs, u32 wls,
                                         int m0, int c0w, int lane,
                                         float (*acc)[4]) {
    const u32 arow  = (u32)(m0 + (lane & 7) + (lane & 8));
    const u32 arow7 = arow & 7;
    const u32 arowb = arow * 256;
    const u32 acb   = (u32)((lane & 16) >> 4);            // chunk offset 0/1
    const u32 brow  = (u32)(c0w + (lane & 7) + ((lane & 16) >> 1));
    const u32 brow7 = brow & 7;
    const u32 browb = brow * 256;
    const u32 bcb   = (u32)((lane & 8) >> 3);             // chunk offset 0/1
#pragma unroll 2
    for (int k = 0; k < 8; k++) {
        u32 aoff = arowb + (((2u * k + acb) ^ arow7) << 4);
        u32 a0[4], a1[4];
        LDM4(a0, as + aoff);
        LDM4(a1, as + aoff + 4096);                       // +16 rows, same xor
        u32 boff = browb + (((2u * k + bcb) ^ brow7) << 4);
        u32 bh0[4], bl0[4], bh1[4], bl1[4];
        LDM4(bh0, whs + boff);
        LDM4(bl0, wls + boff);
        LDM4(bh1, whs + boff + 4096);
        LDM4(bl1, wls + boff + 4096);
        MMA(acc[0], a0, bh0[0], bh0[1]);
        MMA(acc[0], a0, bl0[0], bl0[1]);
        MMA(acc[1], a0, bh0[2], bh0[3]);
        MMA(acc[1], a0, bl0[2], bl0[3]);
        MMA(acc[2], a0, bh1[0], bh1[1]);
        MMA(acc[2], a0, bl1[0], bl1[1]);
        MMA(acc[3], a0, bh1[2], bh1[3]);
        MMA(acc[3], a0, bl1[2], bl1[3]);
        MMA(acc[4], a1, bh0[0], bh0[1]);
        MMA(acc[4], a1, bl0[0], bl0[1]);
        MMA(acc[5], a1, bh0[2], bh0[3]);
        MMA(acc[5], a1, bl0[2], bl0[3]);
        MMA(acc[6], a1, bh1[0], bh1[1]);
        MMA(acc[6], a1, bl1[0], bl1[1]);
        MMA(acc[7], a1, bh1[2], bh1[3]);
        MMA(acc[7], a1, bl1[2], bl1[3]);
    }
}

#define ZACC(a) { _Pragma("unroll") for (int _i = 0; _i < 8; _i++) \
                  _Pragma("unroll") for (int _j = 0; _j < 4; _j++) (a)[_i][_j] = 0.f; }

// Shared-memory sizes
#define SM1  (6 * WBYTES + 1024 + 4 * PITCHB)  // K1: W1h/l W2h/l A0 A1, taps, halo
#define SM23 (7 * WSZ + 3 * CCH * 4)           // K23: W3h/l Wfbh/l Wfah/l A, taps

// ---------------- K1 (unchanged from R16) -------------------------------------
__device__ __forceinline__ void prefK1(uint4 pf[4][2], uint4 pfh[2],
                                       const float* __restrict__ x,
                                       int base, int tid) {
#pragma unroll
    for (int c = 0; c < 4; c++) {
        int q = tid + c * NT;
        int m = q >> 4, k0 = (q & 15) << 3;
        const float* p = x + (size_t)(base + m) * CCH + k0;
        pf[c][0] = *(const uint4*)p;
        pf[c][1] = *(const uint4*)(p + 4);
    }
    if (tid < 32) {
        int sel = tid >> 4;
        int k0 = (tid & 15) << 3;
        long gr = sel ? (long)base + TILE_M : (long)base - 1;
        if ((unsigned long)gr < (unsigned long)NTOK) {
            const float* p = x + gr * CCH + k0;
            pfh[0] = *(const uint4*)p;
            pfh[1] = *(const uint4*)(p + 4);
        } else {
            pfh[0] = make_uint4(0, 0, 0, 0);
            pfh[1] = make_uint4(0, 0, 0, 0);
        }
    }
}

__global__ void __launch_bounds__(NT)
K1(const float* __restrict__ x, const float* __restrict__ wdw) {
    extern __shared__ char sm[];
    char* W1h = sm;
    char* W1l = sm + WBYTES;
    char* W2h = sm + 2 * WBYTES;
    char* W2l = sm + 3 * WBYTES;
    char* A0  = sm + 4 * WBYTES;
    char* A1  = sm + 5 * WBYTES;
    __half2* tap2 = (__half2*)(sm + 6 * WBYTES);
    char* haloH = sm + 6 * WBYTES + 1024;

    const int tid = threadIdx.x, lane = tid & 31, warp = tid >> 5;
    const int m0 = (warp & 3) * 32, c0w = (warp >> 2) * 32;
    const int g = lane >> 2, t = lane & 3;

    loadW(W1h, W1l, 0, tid);
    loadW(W2h, W2l, 1, tid);
    for (int e = tid; e < 3 * 64; e += NT) {
        int k = e >> 6, cp = e & 63, ch = cp * 2;
        tap2[e] = __floats2half2_rn(wdw[ch * 9 + k * 3 + 1],
                                    wdw[(ch + 1) * 9 + k * 3 + 1]);
    }

    const u32 a0s = smem_u32(A0), a1s = smem_u32(A1);
    const u32 w1hs = smem_u32(W1h), w1ls = smem_u32(W1l);
    const u32 w2hs = smem_u32(W2h), w2ls = smem_u32(W2l);
    const __half2 z2 = __float2half2_rn(0.f);

    uint4 pf[4][2], pfh[2];
    int tile = blockIdx.x;
    if (tile < NTILES) prefK1(pf, pfh, x, tile * TILE_M, tid);

    for (; tile < NTILES; tile += gridDim.x) {
        const int base = tile * TILE_M;

#pragma unroll
        for (int c = 0; c < 4; c++) {
            int q = tid + c * NT;
            int m = q >> 4, k0 = (q & 15) << 3;
            uint4 hx = pack8h((const float*)pf[c]);
            *(uint4*)(A1 + (u32)(m * PITCHB + k0) * 2) = hx;
            *(uint4*)(g_xh + (size_t)(base + m) * CCH + k0) = hx;
        }
        if (tid < 32) {
            int sel = tid >> 4, k0 = (tid & 15) << 3;
            *(uint4*)(haloH + (u32)(sel * PITCHB + k0) * 2) =
                pack8h((const float*)pfh);
        }
        __syncthreads();

        float acc[8][4];
        ZACC(acc);
        u32 mb;
        sweep_mask(a1s, w2hs, w2ls, m0, c0w, lane, base, g, t, acc, &mb);

        u32 cX[16];
#pragma unroll
        for (int f = 0; f < 8; f++) {
            float v00 = ((mb >> (f * 4 + 0)) & 1u) ? fmaxf(acc[f][0], 0.f) : 0.f;
            float v01 = ((mb >> (f * 4 + 1)) & 1u) ? fmaxf(acc[f][1], 0.f) : 0.f;
            float v10 = ((mb >> (f * 4 + 2)) & 1u) ? fmaxf(acc[f][2], 0.f) : 0.f;
            float v11 = ((mb >> (f * 4 + 3)) & 1u) ? fmaxf(acc[f][3], 0.f) : 0.f;
            __half2 lo = __floats2half2_rn(v00, v01);
            __half2 hi = __floats2half2_rn(v10, v11);
            cX[2 * f]     = *(u32*)&lo;
            cX[2 * f + 1] = *(u32*)&hi;
        }

#pragma unroll 1
        for (int c = 0; c < 4; c++) {
            int q = tid + c * NT;
            int m = q >> 4, k0 = (q & 15) << 3;
            u32 offm = (u32)(m * PITCHB + k0) * 2;
            uint4 rm = (m == 0)
                ? *(const uint4*)(haloH + (u32)k0 * 2)
                : *(const uint4*)(A1 + offm - PITCHB * 2);
            uint4 md = *(const uint4*)(A1 + offm);
            uint4 rp = (m == TILE_M - 1)
                ? *(const uint4*)(haloH + (u32)(PITCHB + k0) * 2)
                : *(const uint4*)(A1 + offm + PITCHB * 2);
            uint4 t0v = *(const uint4*)(tap2 + (k0 >> 1));
            uint4 t1v = *(const uint4*)(tap2 + 64 + (k0 >> 1));
            uint4 t2v = *(const uint4*)(tap2 + 128 + (k0 >> 1));
            uint4 o;
            const __half2* ap = (const __half2*)&rm;
            const __half2* bp = (const __half2*)&md;
            const __half2* cp = (const __half2*)&rp;
            const __half2* t0p = (const __half2*)&t0v;
            const __half2* t1p = (const __half2*)&t1v;
            const __half2* t2p = (const __half2*)&t2v;
            __half2* op = (__half2*)&o;
#pragma unroll
            for (int j = 0; j < 4; j++) {
                __half2 r = __hmul2(t0p[j], ap[j]);
                r = __hfma2(t1p[j], bp[j], r);
                r = __hfma2(t2p[j], cp[j], r);
                op[j] = __hmax2(r, z2);
            }
            *(uint4*)(A0 + offm) = o;
        }

        int ntile = tile + gridDim.x;
        if (ntile < NTILES) prefK1(pf, pfh, x, ntile * TILE_M, tid);
        __syncthreads();

        ZACC(acc);
        sweep(a0s, w1hs, w1ls, m0, c0w, lane, acc);

#pragma unroll
        for (int f = 0; f < 8; f++) {
            const int mt = f >> 2, nt = f & 3;
            const int r0 = base + m0 + mt * 16 + g;
            const int c0 = c0w + nt * 8 + t * 2;
            float2 cxl = __half22float2(*(__half2*)&cX[2 * f]);
            float2 cxh = __half22float2(*(__half2*)&cX[2 * f + 1]);
            float v00 = cxl.x, v01 = cxl.y, v10 = cxh.x, v11 = cxh.y;
            if ((mb >> (f * 4 + 0)) & 1u) v00 += fmaxf(acc[f][0], 0.f);
            if ((mb >> (f * 4 + 1)) & 1u) v01 += fmaxf(acc[f][1], 0.f);
            if ((mb >> (f * 4 + 2)) & 1u) v10 += fmaxf(acc[f][2], 0.f);
            if ((mb >> (f * 4 + 3)) & 1u) v11 += fmaxf(acc[f][3], 0.f);
            *(__half2*)(g_b2h + (size_t)r0 * CCH + c0) = __floats2half2_rn(v00, v01);
            *(__half2*)(g_b2h + (size_t)(r0 + 8) * CCH + c0) = __floats2half2_rn(v10, v11);
        }
    }
}

// ---------------- K23: fused b2p + fusion -------------------------------------
__global__ void __launch_bounds__(NT)
K23(const float* __restrict__ wdw, float* __restrict__ out) {
    extern __shared__ char sm[];
    char* W3h = sm;
    char* W3l = sm + WSZ;
    char* Wbh = sm + 2 * WSZ;     // Wfb (fusion, b2p half)
    char* Wbl = sm + 3 * WSZ;
    char* Wah = sm + 4 * WSZ;     // Wfa (fusion, x half)
    char* Wal = sm + 5 * WSZ;
    char* A   = sm + 6 * WSZ;
    float* taps = (float*)(sm + 7 * WSZ);

    const int tid = threadIdx.x, lane = tid & 31, warp = tid >> 5;
    const int m0 = (warp & 3) * 32, c0w = (warp >> 2) * 32;
    const int g = lane >> 2, t = lane & 3;

    loadW_sw(W3h, W3l, 2, tid);
    loadW_sw(Wbh, Wbl, 4, tid);
    loadW_sw(Wah, Wal, 3, tid);
    for (int e = tid; e < 3 * CCH; e += NT)
        taps[e] = wdw[(e & 127) * 9 + (e >> 7) * 3 + 1];

    const u32 as = smem_u32(A);
    const u32 w3hs = smem_u32(W3h), w3ls = smem_u32(W3l);
    const u32 wbhs = smem_u32(Wbh), wbls = smem_u32(Wbl);
    const u32 wahs = smem_u32(Wah), wals = smem_u32(Wal);

    for (int tile = blockIdx.x; tile < NTILES; tile += gridDim.x) {
        const int base = tile * TILE_M;

        // 1. A = fp16(relu(dw2(b2h))), swizzled  (fp32 math — matches old K2)
#pragma unroll 1
        for (int q = tid; q < 2048; q += NT) {
            int m = q >> 4, k0 = (q & 15) << 3;
            long gr = (long)base + m;
            float a[8], b[8], c[8], v[8];
            load8h(a, g_b2h, gr - 1, k0);
            load8h(b, g_b2h, gr,     k0);
            load8h(c, g_b2h, gr + 1, k0);
#pragma unroll
            for (int j = 0; j < 8; j++) {
                int ch = k0 + j;
                v[j] = fmaxf(taps[ch] * a[j] + taps[CCH + ch] * b[j]
                             + taps[2 * CCH + ch] * c[j], 0.f);
            }
            u32 doff = (u32)(m * 256 + (((q & 15) ^ (m & 7)) << 4));
            *(uint4*)(A + doff) = pack8h(v);
        }
        __syncthreads();

        // 2. acc1 = A @ W3 ; prefetch xh tile meanwhile
        uint4 pfx[4];
#pragma unroll
        for (int c = 0; c < 4; c++) {
            int q = tid + c * NT;
            int m = q >> 4, k0 = (q & 15) << 3;
            pfx[c] = *(const uint4*)(g_xh + (size_t)(base + m) * CCH + k0);
        }
        float acc1[8][4];
        ZACC(acc1);
        sweep_sw(as, w3hs, w3ls, m0, c0w, lane, acc1);
        __syncthreads();           // all warps done reading A

        // 3. A = fp16(relu(acc1))  (b2p tile, never leaves smem)
#pragma unroll
        for (int f = 0; f < 8; f++) {
            const int mt = f >> 2, nt = f & 3;
            const int lr = m0 + mt * 16 + g;          // local row
            const int c0 = c0w + nt * 8 + t * 2;
            const u32 b0 = (u32)(lr * 256 + (((c0 >> 3) ^ (lr & 7)) << 4)
                                 + (c0 & 7) * 2);
            *(__half2*)(A + b0) =
                __floats2half2_rn(fmaxf(acc1[f][0], 0.f), fmaxf(acc1[f][1], 0.f));
            *(__half2*)(A + b0 + 2048) =                 // +8 rows, same xor
                __floats2half2_rn(fmaxf(acc1[f][2], 0.f), fmaxf(acc1[f][3], 0.f));
        }
        __syncthreads();

        // 4. acc2 = b2p @ Wfb
        float acc2[8][4];
        ZACC(acc2);
        sweep_sw(as, wbhs, wbls, m0, c0w, lane, acc2);
        __syncthreads();           // A free

        // 5. A = xh tile (from prefetch)
#pragma unroll
        for (int c = 0; c < 4; c++) {
            int q = tid + c * NT;
            int m = q >> 4, cc = q & 15;
            u32 doff = (u32)(m * 256 + ((cc ^ (m & 7)) << 4));
            *(uint4*)(A + doff) = pfx[c];
        }
        __syncthreads();

        // 6. acc2 += xh @ Wfa ; out = relu(acc2)
        sweep_sw(as, wahs, wals, m0, c0w, lane, acc2);

#pragma unroll
        for (int f = 0; f < 8; f++) {
            const int mt = f >> 2, nt = f & 3;
            const int r0 = base + m0 + mt * 16 + g;
            const int c0 = c0w + nt * 8 + t * 2;
            *(float2*)(out + (size_t)r0 * CCH + c0) =
                make_float2(fmaxf(acc2[f][0], 0.f), fmaxf(acc2[f][1], 0.f));
            *(float2*)(out + (size_t)(r0 + 8) * CCH + c0) =
                make_float2(fmaxf(acc2[f][2], 0.f), fmaxf(acc2[f][3], 0.f));
        }
        __syncthreads();           // A reused next tile
    }
}

// ---------------- launch ------------------------------------------------------
extern "C" void kernel_launch(void* const* d_in, const int* in_sizes, int n_in,
                              void* d_out, int out_size) {
    const float* x        = (const float*)d_in[0];
    const float* w_b1_dw  = (const float*)d_in[1];
    const float* w_b1_pw  = (const float*)d_in[2];
    const float* w_b2_1x1 = (const float*)d_in[3];
    const float* w_b2_dw  = (const float*)d_in[4];
    const float* w_b2_pw  = (const float*)d_in[5];
    const float* w_fusion = (const float*)d_in[6];
    float*       out      = (float*)d_out;

    cudaFuncSetAttribute(K1,  cudaFuncAttributeMaxDynamicSharedMemorySize, SM1);
    cudaFuncSetAttribute(K23, cudaFuncAttributeMaxDynamicSharedMemorySize, SM23);

    kPrep<<<(5 * CCH * CCH + 255) / 256, 256>>>(w_b1_pw, w_b2_1x1, w_b2_pw, w_fusion);
    K1 <<<GRID1, NT, SM1 >>>(x, w_b1_dw);
    K23<<<GRID1, NT, SM23>>>(w_b2_dw, out);
}